// round 10
// baseline (speedup 1.0000x reference)
#include <cuda_runtime.h>
#include <cstdint>

typedef unsigned long long ULL;

// ---------------- constants ----------------
constexpr int B  = 4;
constexpr int C  = 64;
constexpr int H  = 128;
constexpr int W  = 128;
constexpr int Hp = 130;
constexpr int Wp = 130;
constexpr int O  = 64;
constexpr int N9 = 9;
constexpr int BHW = B * H * W;   // 65536

// fused prep-kernel block ranges
constexpr int NB_OFF = BHW / 256;                 // 256 offset-conv blocks
constexpr int NB_PAD = B * 529;                   // 2116 pad-transpose blocks
constexpr int NB_PW  = (O * C * N9 + 255) / 256;  // 144 weight blocks
constexpr int PREP_SMEM = N9 * C * N9 * 8;        // 41472 B

// k_main smem layout (136 KB, 1 block/SM, 512 threads)
constexpr int SM_X    = 0;        // 2 x 32768 : X[buf][64 c][128 px] swizzled
constexpr int SM_WB   = 65536;    // 2 x 32768 : W[buf][64 k][64 o] dup pairs
constexpr int SM_MIDX = 131072;   // 2 x 2048  : int4  [2][128]
constexpr int SM_MW   = 135168;   // 2 x 2048  : float4[2][128]
constexpr int SM_MAIN = 139264;

// ---------------- scratch (device globals; no allocs) ----------------
__device__ __align__(16) float g_xpad[B * Hp * Wp * C];   // NHWC zero-padded x0
__device__ __align__(16) ULL   g_wTn2[N9 * C * O];        // [n][c][o] -> (w, w) pair
__device__ __align__(16) int4   g_midx[N9 * BHW];         // [n][P] corner offsets
__device__ __align__(16) float4 g_mw[N9 * BHW];           // [n][P] bilinear weights

// ---------------- packed f32x2 helpers ----------------
__device__ __forceinline__ ULL ffma2(ULL a, ULL b, ULL c) {
    ULL d;
    asm("fma.rn.f32x2 %0, %1, %2, %3;" : "=l"(d) : "l"(a), "l"(b), "l"(c));
    return d;
}
__device__ __forceinline__ ULL addf32x2(ULL a, ULL b) {
    ULL d;
    asm("add.rn.f32x2 %0, %1, %2;" : "=l"(d) : "l"(a), "l"(b));
    return d;
}
__device__ __forceinline__ ULL pack2(float lo, float hi) {
    ULL d;
    asm("mov.b64 %0, {%1, %2};" : "=l"(d) : "f"(lo), "f"(hi));
    return d;
}
__device__ __forceinline__ void unpack2(ULL v, float& lo, float& hi) {
    asm("mov.b64 {%0, %1}, %2;" : "=f"(lo), "=f"(hi) : "l"(v));
}

// ============================================================================
// Fused prep kernel (offset conv + meta | pad/transpose | weight reshuffle)
// ============================================================================
__global__ void __launch_bounds__(256) k_prep(const float* __restrict__ x0,
                                              const float* __restrict__ x1,
                                              const float* __restrict__ p_w,
                                              const float* __restrict__ p_b,
                                              const float* __restrict__ conv_w) {
    extern __shared__ char dsm[];
    int t = threadIdx.x;
    int bid = blockIdx.x;

    if (bid < NB_OFF) {
        // ---------------- offset conv + metadata ----------------
        ULL* wsm = (ULL*)dsm;   // [n][c][kk] paired weights, 41472 B
        for (int e = t; e < N9 * C * N9; e += 256)
            wsm[e] = pack2(p_w[e], p_w[e + 5184]);
        __syncthreads();

        int P = bid * 256 + t;
        int b = P >> 14;
        int rem = P & 16383;
        int i = rem >> 7;
        int j = rem & 127;

        ULL acc[9];
        #pragma unroll
        for (int n = 0; n < 9; n++) acc[n] = pack2(p_b[n], p_b[n + 9]);

        const float* x1b = x1 + (b * C * H * W) + i * W + j;
        bool rok0 = (i > 0), rok2 = (i < H - 1), cok0 = (j > 0), cok2 = (j < W - 1);

        #pragma unroll 2
        for (int c = 0; c < C; c++) {
            const float* xc = x1b + c * (H * W);
            float v[9];
            #pragma unroll
            for (int di = 0; di < 3; di++) {
                bool rok = (di == 0) ? rok0 : ((di == 2) ? rok2 : true);
                const float* xr = xc + (di - 1) * W;
                v[di * 3 + 0] = (rok && cok0) ? xr[-1] : 0.f;
                v[di * 3 + 1] = rok ? xr[0] : 0.f;
                v[di * 3 + 2] = (rok && cok2) ? xr[1] : 0.f;
            }
            ULL vd[9];
            #pragma unroll
            for (int k = 0; k < 9; k++) vd[k] = pack2(v[k], v[k]);
            const ULL* wrow = &wsm[c * N9];
            #pragma unroll
            for (int n = 0; n < 9; n++) {
                const ULL* wn = wrow + n * (C * N9);
                #pragma unroll
                for (int k = 0; k < 9; k++)
                    acc[n] = ffma2(vd[k], wn[k], acc[n]);
            }
        }

        int xb130 = b * 130;
        #pragma unroll
        for (int n = 0; n < 9; n++) {
            float ox, oy;
            unpack2(acc[n], ox, oy);
            float px = (float)(i + n / 3) + ox;
            float py = (float)(j + n % 3) + oy;
            float fx = floorf(px), fy = floorf(py);
            int qltx = max(min((int)fx, Hp - 1), 0);
            int qlty = max(min((int)fy, Wp - 1), 0);
            int qrbx = max(min((int)fx + 1, Hp - 1), 0);
            int qrby = max(min((int)fy + 1, Wp - 1), 0);
            float pxc = fminf(fmaxf(px, 0.f), (float)(Hp - 1));
            float pyc = fminf(fmaxf(py, 0.f), (float)(Wp - 1));
            float ax = 1.f + (float)qltx - pxc;
            float bx = 1.f - (float)qrbx + pxc;
            float ay = 1.f + (float)qlty - pyc;
            float by = 1.f - (float)qrby + pyc;
            int4 idx;
            idx.x = ((xb130 + qltx) * 130 + qlty) * 64;
            idx.y = ((xb130 + qrbx) * 130 + qrby) * 64;
            idx.z = ((xb130 + qltx) * 130 + qrby) * 64;
            idx.w = ((xb130 + qrbx) * 130 + qlty) * 64;
            float4 wv;
            wv.x = ax * ay;
            wv.y = bx * by;
            wv.z = ax * by;
            wv.w = bx * ay;
            g_midx[n * BHW + P] = idx;
            g_mw[n * BHW + P]   = wv;
        }
    } else if (bid < NB_OFF + NB_PAD) {
        // ---------------- pad + transpose ----------------
        float (*tile)[33] = (float(*)[33])dsm;
        int bp = bid - NB_OFF;
        int b  = bp / 529;
        int p0 = (bp - b * 529) * 32;
        int tx = t & 31;
        int ty = t >> 5;

        #pragma unroll
        for (int cc = ty; cc < 64; cc += 8) {
            int p = p0 + tx;
            float v = 0.f;
            if (p < Hp * Wp) {
                int y = p / Wp, x = p - (p / Wp) * Wp;
                if (y >= 1 && y <= H && x >= 1 && x <= W)
                    v = x0[((b * C + cc) * H + (y - 1)) * W + (x - 1)];
            }
            tile[cc][tx] = v;
        }
        __syncthreads();

        int base = (b * Hp * Wp + p0) * 64;
        for (int e = t; e < 32 * 64; e += 256) {
            int pl = e >> 6, c = e & 63;
            if (p0 + pl < Hp * Wp)
                g_xpad[base + pl * 64 + c] = tile[c][pl];
        }
    } else {
        // ---------------- conv_w reshuffle ----------------
        int idx = (bid - NB_OFF - NB_PAD) * 256 + t;
        if (idx < O * C * N9) {
            int o = idx / (C * N9);
            int c = (idx / N9) % C;
            int n = idx % N9;
            float w = conv_w[idx];
            g_wTn2[(n * C + c) * O + o] = pack2(w, w);
        }
    }
}

// producer-side gather of one tap into an X buffer (thread pt in 0..255)
__device__ __forceinline__ void gather_tap(char* xdst, const int4* midx_s,
                                           const float4* mw_s, const float* xb,
                                           int lg, int hg, int xorc) {
    #pragma unroll 1
    for (int j = 0; j < 2; j++) {
        float rr[4][4];
        #pragma unroll
        for (int jj = 0; jj < 4; jj++) {
            int px = hg * 8 + j * 4 + jj;
            int4   id = midx_s[px];
            float4 g  = mw_s[px];
            float4 v0 = *(const float4*)(xb + id.x);
            float4 v1 = *(const float4*)(xb + id.y);
            float4 v2 = *(const float4*)(xb + id.z);
            float4 v3 = *(const float4*)(xb + id.w);
            rr[jj][0] = g.x * v0.x + g.y * v1.x + g.z * v2.x + g.w * v3.x;
            rr[jj][1] = g.x * v0.y + g.y * v1.y + g.z * v2.y + g.w * v3.y;
            rr[jj][2] = g.x * v0.z + g.y * v1.z + g.z * v2.z + g.w * v3.z;
            rr[jj][3] = g.x * v0.w + g.y * v1.w + g.z * v2.w + g.w * v3.w;
        }
        int chunk = (hg * 2 + j) ^ xorc;
        #pragma unroll
        for (int q = 0; q < 4; q++) {
            *(float4*)(xdst + ((lg * 4 + q) << 9) + (chunk << 4)) =
                make_float4(rr[0][q], rr[1][q], rr[2][q], rr[3][q]);
        }
    }
}

// ============================================================================
// k_main: warp-specialized, k-split consumers. 512 threads, 1 block/SM.
//  consumers (warps 0-7): warp = 16 outputs x 128 px x half the k-range.
//    per k-step: 1 LDS.128 X (4 wf) + 8 uniform LDS.128 W + 32 FFMA2
//    -> consumer crossbar 3072 cyc/tap < FMA 4096 cyc/tap.
//  producers (warps 8-15): stage meta/W(n+1) + gather X(n+1) (double-buffered).
//  k-halves merged once at the end through smem (X buffer reuse).
// ============================================================================
__global__ void __launch_bounds__(512, 1) k_main(float* __restrict__ out) {
    extern __shared__ char dsm[];
    char*   xbufs  = dsm + SM_X;
    ULL*    wbufs  = (ULL*)(dsm + SM_WB);
    int4*   midx_s = (int4*)(dsm + SM_MIDX);    // [2][128]
    float4* mw_s   = (float4*)(dsm + SM_MW);    // [2][128]

    int t = threadIdx.x;
    int bid = blockIdx.x;             // 512 blocks
    int i = bid & 127;
    int b = bid >> 7;
    int pixbase = (b * H + i) * W;

    // consumer identity
    int warp = t >> 5;
    int lane = t & 31;
    int kh = (warp >> 2) & 1;         // k-half
    int wg = warp & 3;                // output 16-group
    ULL acc[16][2];
    #pragma unroll
    for (int r = 0; r < 16; r++) { acc[r][0] = 0ull; acc[r][1] = 0ull; }

    // producer identity
    int pt = t - 256;                 // 0..255 for producers
    int lg = pt & 15;
    int hg = (pt >> 4) & 15;
    int xorc = lg & 7;
    const float* xbg = g_xpad + lg * 4;

    // ---------------- prologue: producers fill buffer 0 ----------------
    if (t >= 256) {
        if (pt < 128) midx_s[pt] = g_midx[pixbase + pt];
        else          mw_s[pt - 128] = g_mw[pixbase + (pt - 128)];
        const float4* wsrc = (const float4*)g_wTn2;
        float4* wdst = (float4*)wbufs;
        #pragma unroll
        for (int k2 = 0; k2 < 8; k2++) wdst[pt + k2 * 256] = wsrc[pt + k2 * 256];
        asm volatile("bar.sync 1, 256;" ::: "memory");
        gather_tap(xbufs, midx_s, mw_s, xbg, lg, hg, xorc);
    }
    __syncthreads();

    // ---------------- tap loop ----------------
    #pragma unroll 1
    for (int n = 0; n < 9; n++) {
        if (t < 256) {
            // ===== consumer GEMM: k = kh*32 .. +31, o = wg*16 .. +15 =====
            const char* xk0 = xbufs + (n & 1) * 32768 + (kh << 14);      // kh*32*512
            const ULL*  wsb = wbufs + (n & 1) * 4096 + (kh << 11) + (wg << 4);
            #pragma unroll 2
            for (int kk = 0; kk < 32; kk++) {
                int k = (kh << 5) + kk;
                int xk = (k >> 2) & 7;
                ulonglong2 xA = *(const ulonglong2*)(xk0 + (kk << 9) + ((lane ^ xk) << 4));
                const ULL* wr = wsb + (kk << 6);
                ulonglong2 wv[8];
                #pragma unroll
                for (int q = 0; q < 8; q++) wv[q] = *(const ulonglong2*)(wr + q * 2);
                #pragma unroll
                for (int q = 0; q < 8; q++) {
                    acc[2 * q][0]     = ffma2(xA.x, wv[q].x, acc[2 * q][0]);
                    acc[2 * q][1]     = ffma2(xA.y, wv[q].x, acc[2 * q][1]);
                    acc[2 * q + 1][0] = ffma2(xA.x, wv[q].y, acc[2 * q + 1][0]);
                    acc[2 * q + 1][1] = ffma2(xA.y, wv[q].y, acc[2 * q + 1][1]);
                }
            }
        } else if (n < 8) {
            // ===== producers: stage meta/W(n+1), gather X(n+1) =====
            int nxt = (n + 1) & 1;
            if (pt < 128) midx_s[nxt * 128 + pt] = g_midx[(n + 1) * BHW + pixbase + pt];
            else          mw_s[nxt * 128 + (pt - 128)] = g_mw[(n + 1) * BHW + pixbase + (pt - 128)];
            {
                const float4* wsrc = (const float4*)(g_wTn2 + (n + 1) * 4096);
                float4* wdst = (float4*)(wbufs + nxt * 4096);
                #pragma unroll
                for (int k2 = 0; k2 < 8; k2++) wdst[pt + k2 * 256] = wsrc[pt + k2 * 256];
            }
            asm volatile("bar.sync 1, 256;" ::: "memory");
            gather_tap(xbufs + nxt * 32768, midx_s + nxt * 128, mw_s + nxt * 128,
                       xbg, lg, hg, xorc);
        }
        __syncthreads();   // tap boundary
    }

    // ---------------- k-half reduction + output ----------------
    // kh==1 warps park their partials in smem (reuse X buffer region)
    if (t < 256 && kh == 1) {
        char* red = xbufs + (wg << 13);           // wg * 8192
        #pragma unroll
        for (int r = 0; r < 16; r++) {
            ulonglong2 u;
            u.x = acc[r][0];
            u.y = acc[r][1];
            *(ulonglong2*)(red + (r << 9) + (lane << 4)) = u;
        }
    }
    __syncthreads();
    if (t < 256 && kh == 0) {
        const char* red = xbufs + (wg << 13);
        float* ob = out + ((b * O + wg * 16) * H + i) * W + lane * 4;
        #pragma unroll
        for (int r = 0; r < 16; r++) {
            ulonglong2 u = *(const ulonglong2*)(red + (r << 9) + (lane << 4));
            ULL s0 = addf32x2(acc[r][0], u.x);
            ULL s1 = addf32x2(acc[r][1], u.y);
            float4 v;
            unpack2(s0, v.x, v.y);
            unpack2(s1, v.z, v.w);
            *(float4*)(ob + r * (H * W)) = v;
        }
    }
}

// ============================================================================
extern "C" void kernel_launch(void* const* d_in, const int* in_sizes, int n_in,
                              void* d_out, int out_size) {
    const float* x0     = (const float*)d_in[0];
    const float* x1     = (const float*)d_in[1];
    const float* p_w    = (const float*)d_in[2];
    const float* p_b    = (const float*)d_in[3];
    const float* conv_w = (const float*)d_in[4];
    float* out = (float*)d_out;

    cudaFuncSetAttribute(k_main, cudaFuncAttributeMaxDynamicSharedMemorySize, SM_MAIN);

    k_prep<<<NB_OFF + NB_PAD + NB_PW, 256, PREP_SMEM>>>(x0, x1, p_w, p_b, conv_w);
    k_main<<<B * H, 512, SM_MAIN>>>(out);
}

// round 11
// speedup vs baseline: 1.0593x; 1.0593x over previous
#include <cuda_runtime.h>
#include <cstdint>

typedef unsigned long long ULL;

// ---------------- constants ----------------
constexpr int B  = 4;
constexpr int C  = 64;
constexpr int H  = 128;
constexpr int W  = 128;
constexpr int Hp = 130;
constexpr int Wp = 130;
constexpr int O  = 64;
constexpr int N9 = 9;
constexpr int BHW = B * H * W;   // 65536

// fused prep-kernel block ranges
constexpr int NB_OFF = BHW / 512;                 // 128 offset-conv blocks (2 px/thread)
constexpr int NB_PAD = B * 529;                   // 2116 pad-transpose blocks
constexpr int NB_PW  = (O * C * N9 + 255) / 256;  // 144 weight blocks
constexpr int PREP_SMEM = N9 * C * N9 * 8;        // 41472 B

// k_main smem layout (R8: 72 KB total, 2 blocks/SM)
constexpr int SM_W    = 0;        // 32768 : [k][64 o] duplicated pairs
constexpr int SM_X    = 32768;    // 32768 : [64 c][128 px] 16B-chunk XOR swizzled
constexpr int SM_MIDX = 65536;    // 4096  : int4  [2][128]
constexpr int SM_MW   = 69632;    // 4096  : float4[2][128]
constexpr int SM_MAIN = 73728;

// ---------------- scratch (device globals; no allocs) ----------------
__device__ __align__(16) float g_xpad[B * Hp * Wp * C];   // NHWC zero-padded x0
__device__ __align__(16) ULL   g_wTn2[N9 * C * O];        // [n][c][o] -> (w, w) pair
__device__ __align__(16) int4   g_midx[N9 * BHW];         // [n][P] corner offsets
__device__ __align__(16) float4 g_mw[N9 * BHW];           // [n][P] bilinear weights

// ---------------- packed f32x2 helpers ----------------
__device__ __forceinline__ ULL ffma2(ULL a, ULL b, ULL c) {
    ULL d;
    asm("fma.rn.f32x2 %0, %1, %2, %3;" : "=l"(d) : "l"(a), "l"(b), "l"(c));
    return d;
}
__device__ __forceinline__ ULL pack2(float lo, float hi) {
    ULL d;
    asm("mov.b64 %0, {%1, %2};" : "=l"(d) : "f"(lo), "f"(hi));
    return d;
}
__device__ __forceinline__ void unpack2(ULL v, float& lo, float& hi) {
    asm("mov.b64 {%0, %1}, %2;" : "=f"(lo), "=f"(hi) : "l"(v));
}

// meta computation + store for one pixel
__device__ __forceinline__ void emit_meta(const ULL* acc, int P, int b, int i, int j) {
    int xb130 = b * 130;
    #pragma unroll
    for (int n = 0; n < 9; n++) {
        float ox, oy;
        unpack2(acc[n], ox, oy);
        float px = (float)(i + n / 3) + ox;
        float py = (float)(j + n % 3) + oy;
        float fx = floorf(px), fy = floorf(py);
        int qltx = max(min((int)fx, Hp - 1), 0);
        int qlty = max(min((int)fy, Wp - 1), 0);
        int qrbx = max(min((int)fx + 1, Hp - 1), 0);
        int qrby = max(min((int)fy + 1, Wp - 1), 0);
        float pxc = fminf(fmaxf(px, 0.f), (float)(Hp - 1));
        float pyc = fminf(fmaxf(py, 0.f), (float)(Wp - 1));
        float ax = 1.f + (float)qltx - pxc;
        float bx = 1.f - (float)qrbx + pxc;
        float ay = 1.f + (float)qlty - pyc;
        float by = 1.f - (float)qrby + pyc;
        int4 idx;
        idx.x = ((xb130 + qltx) * 130 + qlty) * 64;
        idx.y = ((xb130 + qrbx) * 130 + qrby) * 64;
        idx.z = ((xb130 + qltx) * 130 + qrby) * 64;
        idx.w = ((xb130 + qrbx) * 130 + qlty) * 64;
        float4 wv;
        wv.x = ax * ay;
        wv.y = bx * by;
        wv.z = ax * by;
        wv.w = bx * ay;
        g_midx[n * BHW + P] = idx;
        g_mw[n * BHW + P]   = wv;
    }
}

// ============================================================================
// Fused prep kernel:
//  [0, NB_OFF)   offset conv + bilinear meta, 2 adjacent pixels per thread
//                (shares 6/9 input taps and ALL smem W reads between the px)
//  [+NB_PAD)     pad + NCHW->NHWC transpose of x0
//  [+NB_PW)      conv_w -> duplicated-pair reshuffle
// ============================================================================
__global__ void __launch_bounds__(256) k_prep(const float* __restrict__ x0,
                                              const float* __restrict__ x1,
                                              const float* __restrict__ p_w,
                                              const float* __restrict__ p_b,
                                              const float* __restrict__ conv_w) {
    extern __shared__ char dsm[];
    int t = threadIdx.x;
    int bid = blockIdx.x;

    if (bid < NB_OFF) {
        // ---------------- offset conv + metadata (2 px / thread) ----------------
        ULL* wsm = (ULL*)dsm;   // [n][c][kk] paired weights, 41472 B
        for (int e = t; e < N9 * C * N9; e += 256)
            wsm[e] = pack2(p_w[e], p_w[e + 5184]);
        __syncthreads();

        int Q = bid * 256 + t;            // pixel-pair index, 0..32767
        int P0 = Q * 2;                   // even pixel
        int b = P0 >> 14;
        int rem = P0 & 16383;
        int i = rem >> 7;
        int j0 = rem & 127;               // even, j1 = j0+1 <= 127

        ULL acc0[9], acc1[9];
        #pragma unroll
        for (int n = 0; n < 9; n++) {
            ULL bias = pack2(p_b[n], p_b[n + 9]);
            acc0[n] = bias;
            acc1[n] = bias;
        }

        const float* x1b = x1 + (b * C * H * W) + i * W + j0;
        bool rok0 = (i > 0), rok2 = (i < H - 1);
        bool cokL = (j0 > 0), cokR = (j0 < W - 2);

        #pragma unroll 1
        for (int c = 0; c < C; c++) {
            const float* xc = x1b + c * (H * W);
            // 12 unique taps: cols {j0-1, j0, j0+1, j0+2} x rows {i-1, i, i+1}
            ULL uL[3], u0[3], u1[3], uR[3];
            #pragma unroll
            for (int d = 0; d < 3; d++) {
                bool rok = (d == 0) ? rok0 : ((d == 2) ? rok2 : true);
                const float* xr = xc + (d - 1) * W;
                float vL = (rok && cokL) ? xr[-1] : 0.f;
                float v0 = rok ? xr[0] : 0.f;
                float v1 = rok ? xr[1] : 0.f;
                float vR = (rok && cokR) ? xr[2] : 0.f;
                uL[d] = pack2(vL, vL);
                u0[d] = pack2(v0, v0);
                u1[d] = pack2(v1, v1);
                uR[d] = pack2(vR, vR);
            }
            const ULL* wrow = &wsm[c * N9];
            #pragma unroll
            for (int n = 0; n < 9; n++) {
                const ULL* wn = wrow + n * (C * N9);
                #pragma unroll
                for (int d = 0; d < 3; d++) {
                    ULL wa = wn[3 * d + 0];
                    ULL wb = wn[3 * d + 1];
                    ULL wc = wn[3 * d + 2];
                    acc0[n] = ffma2(uL[d], wa, acc0[n]);
                    acc1[n] = ffma2(u0[d], wa, acc1[n]);
                    acc0[n] = ffma2(u0[d], wb, acc0[n]);
                    acc1[n] = ffma2(u1[d], wb, acc1[n]);
                    acc0[n] = ffma2(u1[d], wc, acc0[n]);
                    acc1[n] = ffma2(uR[d], wc, acc1[n]);
                }
            }
        }

        emit_meta(acc0, P0, b, i, j0);
        emit_meta(acc1, P0 + 1, b, i, j0 + 1);
    } else if (bid < NB_OFF + NB_PAD) {
        // ---------------- pad + transpose ----------------
        float (*tile)[33] = (float(*)[33])dsm;
        int bp = bid - NB_OFF;
        int b  = bp / 529;
        int p0 = (bp - b * 529) * 32;
        int tx = t & 31;
        int ty = t >> 5;

        #pragma unroll
        for (int cc = ty; cc < 64; cc += 8) {
            int p = p0 + tx;
            float v = 0.f;
            if (p < Hp * Wp) {
                int y = p / Wp, x = p - (p / Wp) * Wp;
                if (y >= 1 && y <= H && x >= 1 && x <= W)
                    v = x0[((b * C + cc) * H + (y - 1)) * W + (x - 1)];
            }
            tile[cc][tx] = v;
        }
        __syncthreads();

        int base = (b * Hp * Wp + p0) * 64;
        for (int e = t; e < 32 * 64; e += 256) {
            int pl = e >> 6, c = e & 63;
            if (p0 + pl < Hp * Wp)
                g_xpad[base + pl * 64 + c] = tile[c][pl];
        }
    } else {
        // ---------------- conv_w reshuffle ----------------
        int idx = (bid - NB_OFF - NB_PAD) * 256 + t;
        if (idx < O * C * N9) {
            int o = idx / (C * N9);
            int c = (idx / N9) % C;
            int n = idx % N9;
            float w = conv_w[idx];
            g_wTn2[(n * C + c) * O + o] = pack2(w, w);
        }
    }
}

// ============================================================================
// k_main: 1-row blocks (128 px x 64 o), 256 threads, grid 512, smem-staged
// double-buffered meta, tap-major gather + broadcast-W GEMM.  (R8 verbatim —
// best measured variant.)
// ============================================================================
__global__ void __launch_bounds__(256, 2) k_main(float* __restrict__ out) {
    extern __shared__ char dsm[];
    ULL*    ws2    = (ULL*)(dsm + SM_W);
    char*   xoffb  = dsm + SM_X;
    int4*   midx_s = (int4*)(dsm + SM_MIDX);    // [2][128]
    float4* mw_s   = (float4*)(dsm + SM_MW);    // [2][128]

    int t = threadIdx.x;
    int warp = t >> 5;
    int lane = t & 31;
    int bid = blockIdx.x;             // 512 blocks
    int i = bid & 127;
    int b = bid >> 7;
    int pixbase = (b * H + i) * W;

    int lg = t & 15;                  // gather: channel quad (c = lg*4)
    int hg = t >> 4;                  // gather: 8-px group (px = hg*8..+7)
    int xorc = lg & 7;

    ULL acc[8][2];
    #pragma unroll
    for (int r = 0; r < 8; r++) { acc[r][0] = 0ull; acc[r][1] = 0ull; }

    const float* xb = g_xpad + lg * 4;

    // prologue: stage meta(0) into buffer 0 (half threads idx, half weights)
    if (t < 128) midx_s[t] = g_midx[pixbase + t];
    else         mw_s[t - 128] = g_mw[pixbase + (t - 128)];
    __syncthreads();

    #pragma unroll 1
    for (int n = 0; n < 9; n++) {
        int cur = n & 1, nxt = cur ^ 1;

        // ---- phase 1: stage W(n), prefetch meta(n+1), gather X(n) ----
        {
            const float4* wsrc = (const float4*)(g_wTn2 + n * 4096);
            float4* wdst = (float4*)(dsm + SM_W);
            #pragma unroll
            for (int k2 = 0; k2 < 8; k2++) wdst[t + k2 * 256] = wsrc[t + k2 * 256];
        }
        if (n < 8) {
            if (t < 128) midx_s[nxt * 128 + t] = g_midx[(n + 1) * BHW + pixbase + t];
            else         mw_s[nxt * 128 + (t - 128)] = g_mw[(n + 1) * BHW + pixbase + (t - 128)];
        }

        #pragma unroll 1
        for (int j = 0; j < 2; j++) {
            float rr[4][4];
            #pragma unroll
            for (int jj = 0; jj < 4; jj++) {
                int px = hg * 8 + j * 4 + jj;
                int4   id = midx_s[cur * 128 + px];
                float4 g  = mw_s[cur * 128 + px];
                float4 v0 = *(const float4*)(xb + id.x);
                float4 v1 = *(const float4*)(xb + id.y);
                float4 v2 = *(const float4*)(xb + id.z);
                float4 v3 = *(const float4*)(xb + id.w);
                rr[jj][0] = g.x * v0.x + g.y * v1.x + g.z * v2.x + g.w * v3.x;
                rr[jj][1] = g.x * v0.y + g.y * v1.y + g.z * v2.y + g.w * v3.y;
                rr[jj][2] = g.x * v0.z + g.y * v1.z + g.z * v2.z + g.w * v3.z;
                rr[jj][3] = g.x * v0.w + g.y * v1.w + g.z * v2.w + g.w * v3.w;
            }
            int chunk = (hg * 2 + j) ^ xorc;   // XOR-swizzled 16B chunk (4 px)
            #pragma unroll
            for (int q = 0; q < 4; q++) {
                *(float4*)(xoffb + ((lg * 4 + q) << 9) + (chunk << 4)) =
                    make_float4(rr[0][q], rr[1][q], rr[2][q], rr[3][q]);
            }
        }
        __syncthreads();

        // ---- phase 2: GEMM: acc[o=warp*8+r][px lane*4..+3] += w[o,k]*x[k,px] ----
        #pragma unroll 4
        for (int k = 0; k < 64; k++) {
            int xk = (k >> 2) & 7;
            ulonglong2 xA = *(const ulonglong2*)(xoffb + (k << 9) + ((lane ^ xk) << 4));
            const ULL* wr = ws2 + (k << 6) + (warp << 3);      // warp-uniform
            ulonglong2 w01 = *(const ulonglong2*)(wr + 0);
            ulonglong2 w23 = *(const ulonglong2*)(wr + 2);
            ulonglong2 w45 = *(const ulonglong2*)(wr + 4);
            ulonglong2 w67 = *(const ulonglong2*)(wr + 6);
            acc[0][0] = ffma2(xA.x, w01.x, acc[0][0]);
            acc[0][1] = ffma2(xA.y, w01.x, acc[0][1]);
            acc[1][0] = ffma2(xA.x, w01.y, acc[1][0]);
            acc[1][1] = ffma2(xA.y, w01.y, acc[1][1]);
            acc[2][0] = ffma2(xA.x, w23.x, acc[2][0]);
            acc[2][1] = ffma2(xA.y, w23.x, acc[2][1]);
            acc[3][0] = ffma2(xA.x, w23.y, acc[3][0]);
            acc[3][1] = ffma2(xA.y, w23.y, acc[3][1]);
            acc[4][0] = ffma2(xA.x, w45.x, acc[4][0]);
            acc[4][1] = ffma2(xA.y, w45.x, acc[4][1]);
            acc[5][0] = ffma2(xA.x, w45.y, acc[5][0]);
            acc[5][1] = ffma2(xA.y, w45.y, acc[5][1]);
            acc[6][0] = ffma2(xA.x, w67.x, acc[6][0]);
            acc[6][1] = ffma2(xA.y, w67.x, acc[6][1]);
            acc[7][0] = ffma2(xA.x, w67.y, acc[7][0]);
            acc[7][1] = ffma2(xA.y, w67.y, acc[7][1]);
        }
        __syncthreads();
    }

    // ---- write out: o = warp*8+r; px lane*4..+3 (coalesced) ----
    float* ob = out + ((b * O + warp * 8) * H + i) * W + lane * 4;
    #pragma unroll
    for (int r = 0; r < 8; r++) {
        float4 v;
        unpack2(acc[r][0], v.x, v.y);
        unpack2(acc[r][1], v.z, v.w);
        *(float4*)(ob + r * (H * W)) = v;
    }
}

// ============================================================================
extern "C" void kernel_launch(void* const* d_in, const int* in_sizes, int n_in,
                              void* d_out, int out_size) {
    const float* x0     = (const float*)d_in[0];
    const float* x1     = (const float*)d_in[1];
    const float* p_w    = (const float*)d_in[2];
    const float* p_b    = (const float*)d_in[3];
    const float* conv_w = (const float*)d_in[4];
    float* out = (float*)d_out;

    cudaFuncSetAttribute(k_main, cudaFuncAttributeMaxDynamicSharedMemorySize, SM_MAIN);

    k_prep<<<NB_OFF + NB_PAD + NB_PW, 256, PREP_SMEM>>>(x0, x1, p_w, p_b, conv_w);
    k_main<<<B * H, 256, SM_MAIN>>>(out);
}